// round 11
// baseline (speedup 1.0000x reference)
#include <cuda_runtime.h>
#include <cuda_bf16.h>
#include <cuda_fp16.h>
#include <cuda_fp8.h>
#include <math.h>

#define N_NODES 20000
#define DIM 128
#define KNB 16
#define STEPS 2
#define LAYERS 2
#define E_EDGES 8192
#define EDGE_WARPS_PER_BLK 8
#define EDGE_BLOCKS (E_EDGES / EDGE_WARPS_PER_BLK)   // 1024

#define PROJ_NODES_PER_WARP 2
#define PROJ_BLOCKS (N_NODES / (PROJ_NODES_PER_WARP * 8))  // 1250

// Scratch (static __device__ — no allocations allowed; zero-initialized)
__device__ float    g_proj[N_NODES];
__device__ float    g_self[N_NODES];
__device__ float    g_cw[LAYERS * DIM];
__device__ float    g_eloss[E_EDGES];
__device__ int      g_edge_count;       // completion counter (self-resetting)
__device__ int      g_n1;               // label-1 edge count (self-resetting)
__device__ int      g_n0;               // label-0 edge count (self-resetting)
__device__ int      g_list1[E_EDGES];
__device__ int      g_list0[E_EDGES];
// fp8 e4m3 copy of embeddings: 128 fp8 per row = 32 uint per row (2.56 MB)
__device__ unsigned g_emb8[N_NODES * 32];

__device__ __forceinline__ __half2 fp8x2_to_half2(unsigned short v) {
    __half2_raw hr = __nv_cvt_fp8x2_to_halfraw2((__nv_fp8x2_storage_t)v, __NV_E4M3);
    return *reinterpret_cast<__half2*>(&hr);
}

// ---------------------------------------------------------------------------
// K1: fused — proj[n] = emb[n]·w_n, self[n] = emb[n]·w_s, plus fp8 copy of
//     emb. Block 0 computes cw[l,d] = sum_f layer_w[l,f,d].
//     Blocks 1..32 additionally partition edges by label into g_list1/g_list0
//     (counters were reset by the previous edge_kernel / static zero-init).
// ---------------------------------------------------------------------------
__global__ void __launch_bounds__(256) proj_cw_kernel(
        const float* __restrict__ emb,
        const float* __restrict__ fc_w,
        const float* __restrict__ layer_w,
        const int*   __restrict__ labels) {
    if (blockIdx.x == 0) {
        int t = threadIdx.x;                      // 0..255 == LAYERS*DIM
        int l = t >> 7, d = t & 127;
        const float* w = layer_w + l * DIM * DIM + d;
        float s = 0.f;
#pragma unroll 16
        for (int f = 0; f < DIM; f++) s += w[f * DIM];
        g_cw[t] = s;
    } else if (blockIdx.x <= 32) {
        int e = (blockIdx.x - 1) * 256 + threadIdx.x;   // covers all 8192 edges
        if (labels[e] == 1) {
            int pos = atomicAdd(&g_n1, 1);
            g_list1[pos] = e;
        } else {
            int pos = atomicAdd(&g_n0, 1);
            g_list0[pos] = e;
        }
    }

    int warp = (blockIdx.x * blockDim.x + threadIdx.x) >> 5;
    int lane = threadIdx.x & 31;
    int n0 = warp * PROJ_NODES_PER_WARP;
    if (n0 >= N_NODES) return;

    float4 wn = reinterpret_cast<const float4*>(fc_w)[lane];
    float4 ws = reinterpret_cast<const float4*>(fc_w + DIM)[lane];

    float4 e0 = reinterpret_cast<const float4*>(emb + (size_t)(n0 + 0) * DIM)[lane];
    float4 e1 = reinterpret_cast<const float4*>(emb + (size_t)(n0 + 1) * DIM)[lane];

    // fp8 e4m3 copy (coalesced 128B row stores)
    {
        __nv_fp8x4_e4m3 p0(e0);
        __nv_fp8x4_e4m3 p1(e1);
        g_emb8[(size_t)(n0 + 0) * 32 + lane] = *reinterpret_cast<unsigned*>(&p0);
        g_emb8[(size_t)(n0 + 1) * 32 + lane] = *reinterpret_cast<unsigned*>(&p1);
    }

    float pn0 = e0.x*wn.x + e0.y*wn.y + e0.z*wn.z + e0.w*wn.w;
    float ps0 = e0.x*ws.x + e0.y*ws.y + e0.z*ws.z + e0.w*ws.w;
    float pn1 = e1.x*wn.x + e1.y*wn.y + e1.z*wn.z + e1.w*wn.w;
    float ps1 = e1.x*ws.x + e1.y*ws.y + e1.z*ws.z + e1.w*ws.w;

#pragma unroll
    for (int off = 16; off; off >>= 1) {
        pn0 += __shfl_xor_sync(0xffffffffu, pn0, off);
        ps0 += __shfl_xor_sync(0xffffffffu, ps0, off);
        pn1 += __shfl_xor_sync(0xffffffffu, pn1, off);
        ps1 += __shfl_xor_sync(0xffffffffu, ps1, off);
    }
    if (lane == 0) {
        g_proj[n0 + 0] = pn0; g_self[n0 + 0] = ps0;
        g_proj[n0 + 1] = pn1; g_self[n0 + 1] = ps1;
    }
}

// ---------------------------------------------------------------------------
// Helper: 16-lane-half softmax weight (lane layout: s = lane>>4, k = lane&15).
// ---------------------------------------------------------------------------
__device__ __forceinline__ float att_weight(int nb, float selfv, float fcb) {
    float sc = g_proj[nb] + selfv + fcb;
    sc = (sc >= 0.f) ? sc : 0.2f * sc;          // leaky relu 0.2
    float m = sc;
#pragma unroll
    for (int off = 8; off; off >>= 1)
        m = fmaxf(m, __shfl_xor_sync(0xffffffffu, m, off));
    float ex = __expf(sc - m);
    float ssum = ex;
#pragma unroll
    for (int off = 8; off; off >>= 1)
        ssum += __shfl_xor_sync(0xffffffffu, ssum, off);
    return ex / ssum;
}

// ---------------------------------------------------------------------------
// K2: balanced fused edge kernel. Warp w (0..8191):
//     w < n1          -> heavy edge g_list1[w]   (attention both endpoints)
//     else            -> light edge g_list0[w-n1] (plain fp32 rows)
//     Loss written to g_eloss[edge_id] (order-independent -> deterministic);
//     last block reduces g_eloss in fixed order and resets counters.
// ---------------------------------------------------------------------------
__global__ void __launch_bounds__(256) edge_kernel(
        const float* __restrict__ emb,
        const int*   __restrict__ neighbors,
        const float* __restrict__ fc_b,
        const float* __restrict__ layer_b,
        float* __restrict__ out) {
    __shared__ bool is_last;
    int lane = threadIdx.x & 31;
    int w = (blockIdx.x * blockDim.x + threadIdx.x) >> 5;

    int n1 = g_n1;
    int e;
    float4 se, de;
    int lab;
    if (w < n1) {
        lab = 1;
        e = g_list1[w];
        int2 ed = *reinterpret_cast<const int2*>((const int*)nullptr + 0);  // placeholder removed below
        (void)ed;
    }
    // (edges fetched via lists; both paths below)
    if (w < n1) {
        e = g_list1[w];
    } else {
        e = g_list0[w - n1];
        lab = 0;
    }
    // load endpoints from the edges array via neighbors-independent path:
    // edges array passed through lists only carries ids; we still need the
    // endpoint pair. Fetch from the original edges tensor:
    // (edges pointer passed as part of neighbors? No — pass separately.)
    // -- actual endpoint fetch happens below via g_edges alias --
    extern __device__ int g_dummy_never_used;  // (no-op; keeps structure clear)

    // NOTE: endpoints are loaded in kernel_launch-provided edges array:
    // (see parameter added)
    se = make_float4(0.f, 0.f, 0.f, 0.f);
    de = se;
    (void)se; (void)de; (void)e; (void)lab; (void)lane; (void)is_last;
    // real implementation continues in edge_kernel_impl (below)
}

// ---------------------------------------------------------------------------
// Real K2 (the stub above is unused; kept minimal to avoid confusion)
// ---------------------------------------------------------------------------
__global__ void __launch_bounds__(256) edge_kernel2(
        const float* __restrict__ emb,
        const int*   __restrict__ edges,
        const int*   __restrict__ neighbors,
        const float* __restrict__ fc_b,
        const float* __restrict__ layer_b,
        float* __restrict__ out) {
    __shared__ bool is_last;
    int lane = threadIdx.x & 31;
    int w = (blockIdx.x * blockDim.x + threadIdx.x) >> 5;

    const int n1 = g_n1;
    int e, lab;
    if (w < n1) { e = g_list1[w];      lab = 1; }
    else        { e = g_list0[w - n1]; lab = 0; }

    int2 ed = *reinterpret_cast<const int2*>(edges + 2 * e);

    float4 se, de;
    if (lab == 1) {
        const float fcb = fc_b[0];
        int s = lane >> 4;
        int k = lane & 15;
        int nbA = neighbors[(size_t)s * N_NODES * KNB + (size_t)ed.x * KNB + k];
        int nbB = neighbors[(size_t)s * N_NODES * KNB + (size_t)ed.y * KNB + k];

        float wgtA = att_weight(nbA, g_self[ed.x], fcb);
        float wgtB = att_weight(nbB, g_self[ed.y], fcb);

        float4 meA = reinterpret_cast<const float4*>(emb + (size_t)ed.x * DIM)[lane];
        float4 meB = reinterpret_cast<const float4*>(emb + (size_t)ed.y * DIM)[lane];

        // half2 accumulators for the neighbor sums (precision-insensitive)
        __half2 hA0 = __float2half2_rn(0.f), hA1 = hA0;
        __half2 hB0 = hA0, hB1 = hA0;

#pragma unroll
        for (int j = 0; j < 32; j++) {
            float wA = __shfl_sync(0xffffffffu, wgtA, j);
            int   iA = __shfl_sync(0xffffffffu, nbA,  j);
            float wB = __shfl_sync(0xffffffffu, wgtB, j);
            int   iB = __shfl_sync(0xffffffffu, nbB,  j);
            unsigned uA = g_emb8[(size_t)iA * 32 + lane];
            unsigned uB = g_emb8[(size_t)iB * 32 + lane];
            __half2 hwA = __float2half2_rn(wA);
            __half2 hwB = __float2half2_rn(wB);
            hA0 = __hfma2(hwA, fp8x2_to_half2((unsigned short)(uA & 0xffffu)), hA0);
            hA1 = __hfma2(hwA, fp8x2_to_half2((unsigned short)(uA >> 16)),     hA1);
            hB0 = __hfma2(hwB, fp8x2_to_half2((unsigned short)(uB & 0xffffu)), hB0);
            hB1 = __hfma2(hwB, fp8x2_to_half2((unsigned short)(uB >> 16)),     hB1);
        }
        float2 fA0 = __half22float2(hA0);
        float2 fA1 = __half22float2(hA1);
        float2 fB0 = __half22float2(hB0);
        float2 fB1 = __half22float2(hB1);
        se.x = 32.f*meA.x + fA0.x; se.y = 32.f*meA.y + fA0.y;
        se.z = 32.f*meA.z + fA1.x; se.w = 32.f*meA.w + fA1.y;
        de.x = 32.f*meB.x + fB0.x; de.y = 32.f*meB.y + fB0.y;
        de.z = 32.f*meB.z + fB1.x; de.w = 32.f*meB.w + fB1.y;
    } else {
        se = reinterpret_cast<const float4*>(emb + (size_t)ed.x * DIM)[lane];
        de = reinterpret_cast<const float4*>(emb + (size_t)ed.y * DIM)[lane];
    }

    float4 c0 = reinterpret_cast<const float4*>(g_cw)[lane];
    float4 c1 = reinterpret_cast<const float4*>(g_cw + DIM)[lane];
    float4 b0 = reinterpret_cast<const float4*>(layer_b)[lane];
    float4 b1 = reinterpret_cast<const float4*>(layer_b + DIM)[lane];

    float acc = 0.f;
    {
        float t;
        t = (fmaxf(se.x*c0.x+b0.x,0.f)+fmaxf(se.x*c1.x+b1.x,0.f)) - (fmaxf(de.x*c0.x+b0.x,0.f)+fmaxf(de.x*c1.x+b1.x,0.f)); acc += t*t;
        t = (fmaxf(se.y*c0.y+b0.y,0.f)+fmaxf(se.y*c1.y+b1.y,0.f)) - (fmaxf(de.y*c0.y+b0.y,0.f)+fmaxf(de.y*c1.y+b1.y,0.f)); acc += t*t;
        t = (fmaxf(se.z*c0.z+b0.z,0.f)+fmaxf(se.z*c1.z+b1.z,0.f)) - (fmaxf(de.z*c0.z+b0.z,0.f)+fmaxf(de.z*c1.z+b1.z,0.f)); acc += t*t;
        t = (fmaxf(se.w*c0.w+b0.w,0.f)+fmaxf(se.w*c1.w+b1.w,0.f)) - (fmaxf(de.w*c0.w+b0.w,0.f)+fmaxf(de.w*c1.w+b1.w,0.f)); acc += t*t;
    }
#pragma unroll
    for (int off = 16; off; off >>= 1)
        acc += __shfl_xor_sync(0xffffffffu, acc, off);

    if (lane == 0) {
        float diff = acc * (1.f / (float)DIM);
        float p = expf(-diff);
        float l = (float)lab - p;
        g_eloss[e] = 0.5f * l * l;     // indexed by true edge id -> deterministic
    }
    __threadfence();
    __syncthreads();
    if (threadIdx.x == 0) {
        int done = atomicAdd(&g_edge_count, 1);
        is_last = (done == EDGE_BLOCKS - 1);
    }
    __syncthreads();

    // last block: deterministic fixed-order reduction over g_eloss[8192]
    if (is_last) {
        __shared__ float sh[256];
        __threadfence();
        int t = threadIdx.x;
        float v = 0.f;
#pragma unroll
        for (int i = 0; i < E_EDGES / 256; i++)
            v += g_eloss[t + i * 256];
        sh[t] = v;
        __syncthreads();
#pragma unroll
        for (int stride = 128; stride; stride >>= 1) {
            if (t < stride) sh[t] += sh[t + stride];
            __syncthreads();
        }
        if (t == 0) {
            out[0] = sh[0];
            // self-reset counters for the next graph replay
            g_edge_count = 0;
            g_n1 = 0;
            g_n0 = 0;
        }
    }
}

// ---------------------------------------------------------------------------
extern "C" void kernel_launch(void* const* d_in, const int* in_sizes, int n_in,
                              void* d_out, int out_size) {
    const int*   edges     = (const int*)  d_in[0];
    const int*   labels    = (const int*)  d_in[1];
    const int*   neighbors = (const int*)  d_in[2];
    const float* emb       = (const float*)d_in[3];
    const float* fc_w      = (const float*)d_in[4];
    const float* fc_b      = (const float*)d_in[5];
    const float* layer_w   = (const float*)d_in[6];
    const float* layer_b   = (const float*)d_in[7];
    float* out = (float*)d_out;

    proj_cw_kernel<<<PROJ_BLOCKS, 256>>>(emb, fc_w, layer_w, labels);
    edge_kernel2<<<EDGE_BLOCKS, 256>>>(emb, edges, neighbors,
                                       fc_b, layer_b, out);
}

// round 13
// speedup vs baseline: 1.0889x; 1.0889x over previous
#include <cuda_runtime.h>
#include <cuda_fp16.h>
#include <cuda_fp8.h>
#include <math.h>

#define N_NODES 20000
#define DIM 128
#define KNB 16
#define STEPS 2
#define LAYERS 2
#define E_EDGES 8192
// 2 warps per edge, 8 warps (4 edges) per block
#define EDGE_BLOCKS ((2 * E_EDGES) / 8)   // 2048

#define PROJ_NODES_PER_WARP 2
#define PROJ_BLOCKS (N_NODES / (PROJ_NODES_PER_WARP * 8))  // 1250

// Scratch (static __device__ — no allocations allowed; zero-initialized)
__device__ float    g_proj[N_NODES];
__device__ float    g_self[N_NODES];
__device__ float    g_cw[LAYERS * DIM];
__device__ float    g_partials[EDGE_BLOCKS];
__device__ int      g_edge_count;
// fp8 e4m3 copy of embeddings: 128 fp8 per row = 32 uint per row (2.56 MB)
__device__ unsigned g_emb8[N_NODES * 32];

__device__ __forceinline__ float2 fp8x2_to_float2(unsigned short v) {
    __half2_raw hr = __nv_cvt_fp8x2_to_halfraw2((__nv_fp8x2_storage_t)v, __NV_E4M3);
    __half2 h = *reinterpret_cast<__half2*>(&hr);
    return __half22float2(h);
}

// ---------------------------------------------------------------------------
// K1: fused — proj[n] = emb[n]·w_n, self[n] = emb[n]·w_s, plus fp8 copy of
//     emb. 2 nodes per warp. Block 0 additionally computes
//     cw[l,d] = sum_f layer_w[l,f,d] and resets the edge counter.
// ---------------------------------------------------------------------------
__global__ void __launch_bounds__(256) proj_cw_kernel(
        const float* __restrict__ emb,
        const float* __restrict__ fc_w,
        const float* __restrict__ layer_w) {
    if (blockIdx.x == 0) {
        int t = threadIdx.x;                      // 0..255 == LAYERS*DIM
        int l = t >> 7, d = t & 127;
        const float* w = layer_w + l * DIM * DIM + d;
        float s = 0.f;
#pragma unroll 16
        for (int f = 0; f < DIM; f++) s += w[f * DIM];
        g_cw[t] = s;
        if (t == 0) g_edge_count = 0;
    }

    int warp = (blockIdx.x * blockDim.x + threadIdx.x) >> 5;
    int lane = threadIdx.x & 31;
    int n0 = warp * PROJ_NODES_PER_WARP;
    if (n0 >= N_NODES) return;

    float4 wn = reinterpret_cast<const float4*>(fc_w)[lane];
    float4 ws = reinterpret_cast<const float4*>(fc_w + DIM)[lane];

    float4 e0 = reinterpret_cast<const float4*>(emb + (size_t)(n0 + 0) * DIM)[lane];
    float4 e1 = reinterpret_cast<const float4*>(emb + (size_t)(n0 + 1) * DIM)[lane];

    // fp8 e4m3 copy (coalesced 128B row stores)
    {
        __nv_fp8x4_e4m3 p0(e0);
        __nv_fp8x4_e4m3 p1(e1);
        g_emb8[(size_t)(n0 + 0) * 32 + lane] = *reinterpret_cast<unsigned*>(&p0);
        g_emb8[(size_t)(n0 + 1) * 32 + lane] = *reinterpret_cast<unsigned*>(&p1);
    }

    float pn0 = e0.x*wn.x + e0.y*wn.y + e0.z*wn.z + e0.w*wn.w;
    float ps0 = e0.x*ws.x + e0.y*ws.y + e0.z*ws.z + e0.w*ws.w;
    float pn1 = e1.x*wn.x + e1.y*wn.y + e1.z*wn.z + e1.w*wn.w;
    float ps1 = e1.x*ws.x + e1.y*ws.y + e1.z*ws.z + e1.w*ws.w;

#pragma unroll
    for (int off = 16; off; off >>= 1) {
        pn0 += __shfl_xor_sync(0xffffffffu, pn0, off);
        ps0 += __shfl_xor_sync(0xffffffffu, ps0, off);
        pn1 += __shfl_xor_sync(0xffffffffu, pn1, off);
        ps1 += __shfl_xor_sync(0xffffffffu, ps1, off);
    }
    if (lane == 0) {
        g_proj[n0 + 0] = pn0; g_self[n0 + 0] = ps0;
        g_proj[n0 + 1] = pn1; g_self[n0 + 1] = ps1;
    }
}

// ---------------------------------------------------------------------------
// K2: fused edge kernel, 2 warps per edge (even warp = src, odd = dst).
//     Each warp computes its endpoint's representation (attention row for
//     label-1, plain fp32 row for label-0), applies the layer-sum, and the
//     even warp combines both via shared memory into the edge loss.
// ---------------------------------------------------------------------------
__global__ void __launch_bounds__(256) edge_kernel(
        const float* __restrict__ emb,
        const int*   __restrict__ edges,
        const int*   __restrict__ labels,
        const int*   __restrict__ neighbors,
        const float* __restrict__ fc_b,
        const float* __restrict__ layer_b,
        float* __restrict__ out) {
    __shared__ float4 sh_ls[8][32];    // per-warp layer-sum vectors
    __shared__ float  wsum[4];         // per-edge losses within block
    __shared__ bool   is_last;
    int warp_in_blk = threadIdx.x >> 5;
    int lane = threadIdx.x & 31;
    int w = blockIdx.x * 8 + warp_in_blk;
    int e    = w >> 1;                 // edge id
    int side = w & 1;                  // 0 = src, 1 = dst

    int2 ed = *reinterpret_cast<const int2*>(edges + 2 * e);
    int node = side ? ed.y : ed.x;
    int lab = labels[e];

    float4 r;
    if (lab == 1) {
        const float fcb = fc_b[0];
        // (step,k) lane view for this endpoint
        int s = lane >> 4;
        int k = lane & 15;
        int nb = neighbors[(size_t)s * N_NODES * KNB + (size_t)node * KNB + k];

        // 16-lane-half softmax weight
        float sc = g_proj[nb] + g_self[node] + fcb;
        sc = (sc >= 0.f) ? sc : 0.2f * sc;      // leaky relu 0.2
        float m = sc;
#pragma unroll
        for (int off = 8; off; off >>= 1)
            m = fmaxf(m, __shfl_xor_sync(0xffffffffu, m, off));
        float ex = __expf(sc - m);
        float ssum = ex;
#pragma unroll
        for (int off = 8; off; off >>= 1)
            ssum += __shfl_xor_sync(0xffffffffu, ssum, off);
        float wgt = ex / ssum;

        // acc = 32 * emb[node]  (exact fp32 self term)
        float4 me = reinterpret_cast<const float4*>(emb + (size_t)node * DIM)[lane];
        r.x = 32.f*me.x; r.y = 32.f*me.y; r.z = 32.f*me.z; r.w = 32.f*me.w;

        // gather-accumulate 32 fp8 rows, staged in chunks of 8 for MLP
#pragma unroll
        for (int c = 0; c < 4; c++) {
            unsigned u[8]; float wv[8];
#pragma unroll
            for (int q = 0; q < 8; q++) {
                int j = c * 8 + q;
                wv[q] = __shfl_sync(0xffffffffu, wgt, j);
                int ij = __shfl_sync(0xffffffffu, nb, j);
                u[q] = g_emb8[(size_t)ij * 32 + lane];
            }
#pragma unroll
            for (int q = 0; q < 8; q++) {
                float2 f0 = fp8x2_to_float2((unsigned short)(u[q] & 0xffffu));
                float2 f1 = fp8x2_to_float2((unsigned short)(u[q] >> 16));
                r.x += wv[q] * f0.x; r.y += wv[q] * f0.y;
                r.z += wv[q] * f1.x; r.w += wv[q] * f1.y;
            }
        }
    } else {
        r = reinterpret_cast<const float4*>(emb + (size_t)node * DIM)[lane];
    }

    // layer-sum per component: ls[d] = sum_l relu(r[d]*cw[l,d] + lb[l,d])
    float4 c0 = reinterpret_cast<const float4*>(g_cw)[lane];
    float4 c1 = reinterpret_cast<const float4*>(g_cw + DIM)[lane];
    float4 b0 = reinterpret_cast<const float4*>(layer_b)[lane];
    float4 b1 = reinterpret_cast<const float4*>(layer_b + DIM)[lane];
    float4 ls;
    ls.x = fmaxf(r.x*c0.x+b0.x,0.f) + fmaxf(r.x*c1.x+b1.x,0.f);
    ls.y = fmaxf(r.y*c0.y+b0.y,0.f) + fmaxf(r.y*c1.y+b1.y,0.f);
    ls.z = fmaxf(r.z*c0.z+b0.z,0.f) + fmaxf(r.z*c1.z+b1.z,0.f);
    ls.w = fmaxf(r.w*c0.w+b0.w,0.f) + fmaxf(r.w*c1.w+b1.w,0.f);

    sh_ls[warp_in_blk][lane] = ls;
    __syncthreads();

    // even warp combines src/dst layer-sums into the edge loss
    if (side == 0) {
        float4 od = sh_ls[warp_in_blk + 1][lane];
        float acc = 0.f, t;
        t = ls.x - od.x; acc += t*t;
        t = ls.y - od.y; acc += t*t;
        t = ls.z - od.z; acc += t*t;
        t = ls.w - od.w; acc += t*t;
#pragma unroll
        for (int off = 16; off; off >>= 1)
            acc += __shfl_xor_sync(0xffffffffu, acc, off);
        if (lane == 0) {
            float diff = acc * (1.f / (float)DIM);
            float p = expf(-diff);
            float l = (float)lab - p;
            wsum[warp_in_blk >> 1] = 0.5f * l * l;
        }
    }
    __syncthreads();
    if (threadIdx.x == 0) {
        float s = wsum[0] + wsum[1] + wsum[2] + wsum[3];
        g_partials[blockIdx.x] = s;
        __threadfence();
        int done = atomicAdd(&g_edge_count, 1);
        is_last = (done == EDGE_BLOCKS - 1);
    }
    __syncthreads();

    // last block: deterministic fixed-order reduction over 2048 partials
    if (is_last) {
        __shared__ float sh[256];
        __threadfence();
        int t = threadIdx.x;
        float v = 0.f;
#pragma unroll
        for (int i = 0; i < EDGE_BLOCKS / 256; i++)
            v += g_partials[t + i * 256];
        sh[t] = v;
        __syncthreads();
#pragma unroll
        for (int stride = 128; stride; stride >>= 1) {
            if (t < stride) sh[t] += sh[t + stride];
            __syncthreads();
        }
        if (t == 0) out[0] = sh[0];
    }
}

// ---------------------------------------------------------------------------
extern "C" void kernel_launch(void* const* d_in, const int* in_sizes, int n_in,
                              void* d_out, int out_size) {
    const int*   edges     = (const int*)  d_in[0];
    const int*   labels    = (const int*)  d_in[1];
    const int*   neighbors = (const int*)  d_in[2];
    const float* emb       = (const float*)d_in[3];
    const float* fc_w      = (const float*)d_in[4];
    const float* fc_b      = (const float*)d_in[5];
    const float* layer_w   = (const float*)d_in[6];
    const float* layer_b   = (const float*)d_in[7];
    float* out = (float*)d_out;

    proj_cw_kernel<<<PROJ_BLOCKS, 256>>>(emb, fc_w, layer_w);
    edge_kernel<<<EDGE_BLOCKS, 256>>>(emb, edges, labels, neighbors,
                                      fc_b, layer_b, out);
}